// round 1
// baseline (speedup 1.0000x reference)
#include <cuda_runtime.h>
#include <math.h>

// Problem constants
#define BB   2
#define NN   2048
#define DD   2048
#define HH   16
#define DHH  128
#define MTOT (BB*NN)          // 4096 rows of x
#define SCALE 0.08838834764831845f  // DH^-0.5

// ---------------- device scratch (statics: allowed; no runtime alloc) -------
__device__ float g_Q[(size_t)BB*HH*NN*DHH];   // (b,h,n,dh), scale folded in
__device__ float g_K[(size_t)BB*HH*NN*DHH];   // (b,h,n,dh)
__device__ float g_V[(size_t)BB*HH*NN*DHH];   // (b,h,n,dh)
__device__ float g_O[(size_t)MTOT*DD];        // gated, merged heads (m, H*DH)
__device__ float g_gate[(size_t)MTOT*HH];     // sigmoid(x@Wg+bg)

// =====================================================================
// SGEMM core: C(128x128 tile) = A(Mx2048) * W(2048x2048), fp32
// 256 threads, 8x8 microtile, BK=16
// =====================================================================
__global__ __launch_bounds__(256)
void gemm_qkv_kernel(const float* __restrict__ A,
                     const float* __restrict__ Wq,
                     const float* __restrict__ Wk,
                     const float* __restrict__ Wv)
{
    __shared__ float As[16][132];   // transposed A tile, padded
    __shared__ float Bs[16][128];

    const float* Bmat = (blockIdx.z == 0) ? Wq : (blockIdx.z == 1) ? Wk : Wv;
    float* Cdst = (blockIdx.z == 0) ? g_Q : (blockIdx.z == 1) ? g_K : g_V;

    const int tid = threadIdx.x;
    const int tx = tid & 15, ty = tid >> 4;
    const int row0 = blockIdx.y * 128;
    const int col0 = blockIdx.x * 128;

    const int ar  = tid >> 2;          // 0..63
    const int ac4 = (tid & 3) * 4;     // k offset within BK
    const int br  = tid >> 5;          // 0..7
    const int bc4 = (tid & 31) * 4;    // col offset

    float acc[8][8];
#pragma unroll
    for (int i = 0; i < 8; i++)
#pragma unroll
        for (int j = 0; j < 8; j++) acc[i][j] = 0.f;

    for (int k0 = 0; k0 < DD; k0 += 16) {
#pragma unroll
        for (int p = 0; p < 2; p++) {
            int r = ar + p * 64;
            float4 v = *(const float4*)(A + (size_t)(row0 + r) * DD + k0 + ac4);
            As[ac4 + 0][r] = v.x; As[ac4 + 1][r] = v.y;
            As[ac4 + 2][r] = v.z; As[ac4 + 3][r] = v.w;
        }
#pragma unroll
        for (int p = 0; p < 2; p++) {
            int r = br + p * 8;
            *(float4*)&Bs[r][bc4] =
                *(const float4*)(Bmat + (size_t)(k0 + r) * 2048 + col0 + bc4);
        }
        __syncthreads();

#pragma unroll
        for (int k = 0; k < 16; k++) {
            float a[8], b[8];
            *(float4*)(a)     = *(float4*)&As[k][ty * 8];
            *(float4*)(a + 4) = *(float4*)&As[k][ty * 8 + 4];
            *(float4*)(b)     = *(float4*)&Bs[k][tx * 8];
            *(float4*)(b + 4) = *(float4*)&Bs[k][tx * 8 + 4];
#pragma unroll
            for (int i = 0; i < 8; i++)
#pragma unroll
                for (int j = 0; j < 8; j++)
                    acc[i][j] = fmaf(a[i], b[j], acc[i][j]);
        }
        __syncthreads();
    }

    // split-head store: (b,h,n,dh)
#pragma unroll
    for (int i = 0; i < 8; i++) {
        int m = row0 + ty * 8 + i;
        int b = m >> 11, n = m & (NN - 1);
        int c = col0 + tx * 8;
        int h = c >> 7, dh = c & (DHH - 1);
        float* dp = Cdst + (((size_t)(b * HH + h) * NN + n) * DHH + dh);
        *(float4*)dp       = make_float4(acc[i][0], acc[i][1], acc[i][2], acc[i][3]);
        *(float4*)(dp + 4) = make_float4(acc[i][4], acc[i][5], acc[i][6], acc[i][7]);
    }
}

__global__ __launch_bounds__(256)
void gemm_out_kernel(const float* __restrict__ Wo, float* __restrict__ out)
{
    __shared__ float As[16][132];
    __shared__ float Bs[16][128];

    const float* A = g_O;
    const int tid = threadIdx.x;
    const int tx = tid & 15, ty = tid >> 4;
    const int row0 = blockIdx.y * 128;
    const int col0 = blockIdx.x * 128;

    const int ar  = tid >> 2;
    const int ac4 = (tid & 3) * 4;
    const int br  = tid >> 5;
    const int bc4 = (tid & 31) * 4;

    float acc[8][8];
#pragma unroll
    for (int i = 0; i < 8; i++)
#pragma unroll
        for (int j = 0; j < 8; j++) acc[i][j] = 0.f;

    for (int k0 = 0; k0 < DD; k0 += 16) {
#pragma unroll
        for (int p = 0; p < 2; p++) {
            int r = ar + p * 64;
            float4 v = *(const float4*)(A + (size_t)(row0 + r) * DD + k0 + ac4);
            As[ac4 + 0][r] = v.x; As[ac4 + 1][r] = v.y;
            As[ac4 + 2][r] = v.z; As[ac4 + 3][r] = v.w;
        }
#pragma unroll
        for (int p = 0; p < 2; p++) {
            int r = br + p * 8;
            *(float4*)&Bs[r][bc4] =
                *(const float4*)(Wo + (size_t)(k0 + r) * 2048 + col0 + bc4);
        }
        __syncthreads();

#pragma unroll
        for (int k = 0; k < 16; k++) {
            float a[8], b[8];
            *(float4*)(a)     = *(float4*)&As[k][ty * 8];
            *(float4*)(a + 4) = *(float4*)&As[k][ty * 8 + 4];
            *(float4*)(b)     = *(float4*)&Bs[k][tx * 8];
            *(float4*)(b + 4) = *(float4*)&Bs[k][tx * 8 + 4];
#pragma unroll
            for (int i = 0; i < 8; i++)
#pragma unroll
                for (int j = 0; j < 8; j++)
                    acc[i][j] = fmaf(a[i], b[j], acc[i][j]);
        }
        __syncthreads();
    }

#pragma unroll
    for (int i = 0; i < 8; i++) {
        int m = row0 + ty * 8 + i;
        float* dp = out + (size_t)m * DD + col0 + tx * 8;
        *(float4*)dp       = make_float4(acc[i][0], acc[i][1], acc[i][2], acc[i][3]);
        *(float4*)(dp + 4) = make_float4(acc[i][4], acc[i][5], acc[i][6], acc[i][7]);
    }
}

// =====================================================================
// RoPE on Q and K (in place), folding the softmax scale into Q.
// One thread per (b,h,n, dh<64) pair.
// =====================================================================
__global__ void rope_kernel(const float* __restrict__ freqs)
{
    int idx = blockIdx.x * blockDim.x + threadIdx.x;
    const int total = BB * HH * NN * 64;
    if (idx >= total) return;
    int half = idx & 63;
    int n = (idx >> 6) & (NN - 1);
    int bh = idx >> 17;

    const float* f = freqs + (size_t)n * DHH;
    float c1 = cosf(f[half]),      s1 = sinf(f[half]);
    float c2 = cosf(f[half + 64]), s2 = sinf(f[half + 64]);

    size_t base = ((size_t)bh * NN + n) * DHH;
    float q1 = g_Q[base + half], q2 = g_Q[base + half + 64];
    g_Q[base + half]      = (q1 * c1 - q2 * s1) * SCALE;
    g_Q[base + half + 64] = (q2 * c2 + q1 * s2) * SCALE;
    float k1 = g_K[base + half], k2 = g_K[base + half + 64];
    g_K[base + half]      = k1 * c1 - k2 * s1;
    g_K[base + half + 64] = k2 * c2 + k1 * s2;
}

// =====================================================================
// Gate: sigmoid(x @ Wg + bg), one warp per row of x
// =====================================================================
__global__ void gate_kernel(const float* __restrict__ x,
                            const float* __restrict__ Wg,
                            const float* __restrict__ bg)
{
    int gw = (blockIdx.x * blockDim.x + threadIdx.x) >> 5;
    int lane = threadIdx.x & 31;
    if (gw >= MTOT) return;

    const float* xr = x + (size_t)gw * DD;
    float acc[HH];
#pragma unroll
    for (int h = 0; h < HH; h++) acc[h] = 0.f;

    for (int k = lane; k < DD; k += 32) {
        float xv = xr[k];
        const float* w = Wg + (size_t)k * HH;
#pragma unroll
        for (int h = 0; h < HH; h++) acc[h] = fmaf(xv, w[h], acc[h]);
    }
#pragma unroll
    for (int h = 0; h < HH; h++) {
#pragma unroll
        for (int off = 16; off > 0; off >>= 1)
            acc[h] += __shfl_xor_sync(0xffffffffu, acc[h], off);
    }
    if (lane == 0) {
#pragma unroll
        for (int h = 0; h < HH; h++)
            g_gate[(size_t)gw * HH + h] = 1.f / (1.f + expf(-(acc[h] + bg[h])));
    }
}

// =====================================================================
// Flash attention (fp32): Br=Bc=64, DH=128, online softmax.
// Block = 256 threads = 16(ty rows) x 16(tx cols).
// Per-thread: 4 q rows; GEMM1 cols {tx, tx+16, tx+32, tx+48}; GEMM2 cols tx*8..+7
// Epilogue applies 1/l and the sigmoid gate, stores merged-head layout to g_O.
// =====================================================================
#define QS_STRIDE 130
#define KS_STRIDE 130
#define SS_STRIDE 66
#define FLASH_SMEM ((64*QS_STRIDE + 64*KS_STRIDE + 64*128 + 64*SS_STRIDE) * 4)

__global__ __launch_bounds__(256)
void flash_kernel()
{
    extern __shared__ float sm[];
    float* Qs = sm;                       // [64][130]
    float* Ks = Qs + 64 * QS_STRIDE;      // [64][130]
    float* Vs = Ks + 64 * KS_STRIDE;      // [64][128]
    float* Ss = Vs + 64 * 128;            // [64][66]

    const int tid = threadIdx.x;
    const int tx = tid & 15, ty = tid >> 4;

    const int bh = blockIdx.x >> 5;          // b*H + h
    const int n0 = (blockIdx.x & 31) * 64;

    const float* Qg = g_Q + ((size_t)bh * NN + n0) * DHH;
    const float* Kg = g_K + (size_t)bh * NN * DHH;
    const float* Vg = g_V + (size_t)bh * NN * DHH;

    // load Q tile
    {
        int c4 = (tid & 31) * 4;
        int r0 = tid >> 5;
#pragma unroll
        for (int p = 0; p < 8; p++) {
            int r = r0 + p * 8;
            float4 v = *(const float4*)(Qg + (size_t)r * DHH + c4);
            Qs[r * QS_STRIDE + c4 + 0] = v.x;
            Qs[r * QS_STRIDE + c4 + 1] = v.y;
            Qs[r * QS_STRIDE + c4 + 2] = v.z;
            Qs[r * QS_STRIDE + c4 + 3] = v.w;
        }
    }

    float mrow[4], lrow[4], o[4][8];
#pragma unroll
    for (int i = 0; i < 4; i++) {
        mrow[i] = -1e30f; lrow[i] = 0.f;
#pragma unroll
        for (int c = 0; c < 8; c++) o[i][c] = 0.f;
    }

    for (int kt = 0; kt < NN / 64; kt++) {
        __syncthreads();   // protect Ks/Vs from previous iteration's readers
        {
            int c4 = (tid & 31) * 4;
            int r0 = tid >> 5;
            const float* Kt = Kg + (size_t)kt * 64 * DHH;
            const float* Vt = Vg + (size_t)kt * 64 * DHH;
#pragma unroll
            for (int p = 0; p < 8; p++) {
                int r = r0 + p * 8;
                float4 kv = *(const float4*)(Kt + (size_t)r * DHH + c4);
                Ks[r * KS_STRIDE + c4 + 0] = kv.x;
                Ks[r * KS_STRIDE + c4 + 1] = kv.y;
                Ks[r * KS_STRIDE + c4 + 2] = kv.z;
                Ks[r * KS_STRIDE + c4 + 3] = kv.w;
                *(float4*)&Vs[r * 128 + c4] = *(const float4*)(Vt + (size_t)r * DHH + c4);
            }
        }
        __syncthreads();

        // GEMM1: S = Q K^T  (scale already folded into Q)
        float s[4][4];
#pragma unroll
        for (int i = 0; i < 4; i++)
#pragma unroll
            for (int j = 0; j < 4; j++) s[i][j] = 0.f;

#pragma unroll 4
        for (int dh = 0; dh < DHH; dh++) {
            float q0 = Qs[(ty * 4 + 0) * QS_STRIDE + dh];
            float q1 = Qs[(ty * 4 + 1) * QS_STRIDE + dh];
            float q2 = Qs[(ty * 4 + 2) * QS_STRIDE + dh];
            float q3 = Qs[(ty * 4 + 3) * QS_STRIDE + dh];
            float k0 = Ks[(tx)      * KS_STRIDE + dh];
            float k1 = Ks[(tx + 16) * KS_STRIDE + dh];
            float k2 = Ks[(tx + 32) * KS_STRIDE + dh];
            float k3 = Ks[(tx + 48) * KS_STRIDE + dh];
            s[0][0] = fmaf(q0, k0, s[0][0]); s[0][1] = fmaf(q0, k1, s[0][1]);
            s[0][2] = fmaf(q0, k2, s[0][2]); s[0][3] = fmaf(q0, k3, s[0][3]);
            s[1][0] = fmaf(q1, k0, s[1][0]); s[1][1] = fmaf(q1, k1, s[1][1]);
            s[1][2] = fmaf(q1, k2, s[1][2]); s[1][3] = fmaf(q1, k3, s[1][3]);
            s[2][0] = fmaf(q2, k0, s[2][0]); s[2][1] = fmaf(q2, k1, s[2][1]);
            s[2][2] = fmaf(q2, k2, s[2][2]); s[2][3] = fmaf(q2, k3, s[2][3]);
            s[3][0] = fmaf(q3, k0, s[3][0]); s[3][1] = fmaf(q3, k1, s[3][1]);
            s[3][2] = fmaf(q3, k2, s[3][2]); s[3][3] = fmaf(q3, k3, s[3][3]);
        }

        // online softmax (row reductions over the 16 tx lanes)
#pragma unroll
        for (int i = 0; i < 4; i++) {
            float mx = fmaxf(fmaxf(s[i][0], s[i][1]), fmaxf(s[i][2], s[i][3]));
            mx = fmaxf(mx, __shfl_xor_sync(0xffffffffu, mx, 1));
            mx = fmaxf(mx, __shfl_xor_sync(0xffffffffu, mx, 2));
            mx = fmaxf(mx, __shfl_xor_sync(0xffffffffu, mx, 4));
            mx = fmaxf(mx, __shfl_xor_sync(0xffffffffu, mx, 8));
            float mnew = fmaxf(mrow[i], mx);
            float p0 = __expf(s[i][0] - mnew);
            float p1 = __expf(s[i][1] - mnew);
            float p2 = __expf(s[i][2] - mnew);
            float p3 = __expf(s[i][3] - mnew);
            float sum = p0 + p1 + p2 + p3;
            sum += __shfl_xor_sync(0xffffffffu, sum, 1);
            sum += __shfl_xor_sync(0xffffffffu, sum, 2);
            sum += __shfl_xor_sync(0xffffffffu, sum, 4);
            sum += __shfl_xor_sync(0xffffffffu, sum, 8);
            float alpha = __expf(mrow[i] - mnew);
            lrow[i] = lrow[i] * alpha + sum;
            mrow[i] = mnew;
#pragma unroll
            for (int c = 0; c < 8; c++) o[i][c] *= alpha;
            int rb = (ty * 4 + i) * SS_STRIDE + tx;
            Ss[rb]      = p0;
            Ss[rb + 16] = p1;
            Ss[rb + 32] = p2;
            Ss[rb + 48] = p3;
        }
        __syncthreads();

        // GEMM2: O += P V
#pragma unroll 2
        for (int j = 0; j < 64; j++) {
            float p0 = Ss[(ty * 4 + 0) * SS_STRIDE + j];
            float p1 = Ss[(ty * 4 + 1) * SS_STRIDE + j];
            float p2 = Ss[(ty * 4 + 2) * SS_STRIDE + j];
            float p3 = Ss[(ty * 4 + 3) * SS_STRIDE + j];
            float4 v0 = *(float4*)&Vs[j * 128 + tx * 8];
            float4 v1 = *(float4*)&Vs[j * 128 + tx * 8 + 4];
            o[0][0] = fmaf(p0, v0.x, o[0][0]); o[0][1] = fmaf(p0, v0.y, o[0][1]);
            o[0][2] = fmaf(p0, v0.z, o[0][2]); o[0][3] = fmaf(p0, v0.w, o[0][3]);
            o[0][4] = fmaf(p0, v1.x, o[0][4]); o[0][5] = fmaf(p0, v1.y, o[0][5]);
            o[0][6] = fmaf(p0, v1.z, o[0][6]); o[0][7] = fmaf(p0, v1.w, o[0][7]);
            o[1][0] = fmaf(p1, v0.x, o[1][0]); o[1][1] = fmaf(p1, v0.y, o[1][1]);
            o[1][2] = fmaf(p1, v0.z, o[1][2]); o[1][3] = fmaf(p1, v0.w, o[1][3]);
            o[1][4] = fmaf(p1, v1.x, o[1][4]); o[1][5] = fmaf(p1, v1.y, o[1][5]);
            o[1][6] = fmaf(p1, v1.z, o[1][6]); o[1][7] = fmaf(p1, v1.w, o[1][7]);
            o[2][0] = fmaf(p2, v0.x, o[2][0]); o[2][1] = fmaf(p2, v0.y, o[2][1]);
            o[2][2] = fmaf(p2, v0.z, o[2][2]); o[2][3] = fmaf(p2, v0.w, o[2][3]);
            o[2][4] = fmaf(p2, v1.x, o[2][4]); o[2][5] = fmaf(p2, v1.y, o[2][5]);
            o[2][6] = fmaf(p2, v1.z, o[2][6]); o[2][7] = fmaf(p2, v1.w, o[2][7]);
            o[3][0] = fmaf(p3, v0.x, o[3][0]); o[3][1] = fmaf(p3, v0.y, o[3][1]);
            o[3][2] = fmaf(p3, v0.z, o[3][2]); o[3][3] = fmaf(p3, v0.w, o[3][3]);
            o[3][4] = fmaf(p3, v1.x, o[3][4]); o[3][5] = fmaf(p3, v1.y, o[3][5]);
            o[3][6] = fmaf(p3, v1.z, o[3][6]); o[3][7] = fmaf(p3, v1.w, o[3][7]);
        }
    }

    // epilogue: normalize, gate, merge heads
    const int b = bh >> 4, h = bh & 15;
#pragma unroll
    for (int i = 0; i < 4; i++) {
        int n = n0 + ty * 4 + i;
        float g = g_gate[((size_t)(b * NN + n)) * HH + h];
        float sc = g / lrow[i];
        float* dst = g_O + ((size_t)(b * NN + n) * DD + h * DHH + tx * 8);
        *(float4*)dst       = make_float4(o[i][0] * sc, o[i][1] * sc, o[i][2] * sc, o[i][3] * sc);
        *(float4*)(dst + 4) = make_float4(o[i][4] * sc, o[i][5] * sc, o[i][6] * sc, o[i][7] * sc);
    }
}

// =====================================================================
extern "C" void kernel_launch(void* const* d_in, const int* in_sizes, int n_in,
                              void* d_out, int out_size)
{
    const float* x    = (const float*)d_in[0];
    const float* rope = (const float*)d_in[1];
    const float* Wq   = (const float*)d_in[2];
    const float* Wk   = (const float*)d_in[3];
    const float* Wv   = (const float*)d_in[4];
    const float* Wg   = (const float*)d_in[5];
    const float* bg   = (const float*)d_in[6];
    const float* Wo   = (const float*)d_in[7];
    float* out = (float*)d_out;

    cudaFuncSetAttribute(flash_kernel,
                         cudaFuncAttributeMaxDynamicSharedMemorySize, FLASH_SMEM);

    // 1) QKV projections (split-head store)
    dim3 gq(DD / 128, MTOT / 128, 3);
    gemm_qkv_kernel<<<gq, 256>>>(x, Wq, Wk, Wv);

    // 2) RoPE (+ fold softmax scale into Q)
    {
        int total = BB * HH * NN * 64;
        rope_kernel<<<(total + 255) / 256, 256>>>(rope);
    }

    // 3) head gates
    gate_kernel<<<(MTOT * 32 + 255) / 256, 256>>>(x, Wg, bg);

    // 4) flash attention + gating + head merge
    flash_kernel<<<BB * HH * (NN / 64), 256, FLASH_SMEM>>>();

    // 5) output projection
    dim3 go(DD / 128, MTOT / 128);
    gemm_out_kernel<<<go, 256>>>(Wo, out);
}

// round 3
// speedup vs baseline: 1.3926x; 1.3926x over previous
#include <cuda_runtime.h>
#include <math.h>
#include <stdint.h>

// Problem constants
#define BB   2
#define NN   2048
#define DD   2048
#define HH   16
#define DHH  128
#define MTOT (BB*NN)
#define SCALE 0.08838834764831845f  // DH^-0.5

// ---------------- device scratch ----------------
__device__ float g_Q[(size_t)BB*HH*NN*DHH];
__device__ float g_K[(size_t)BB*HH*NN*DHH];
__device__ float g_V[(size_t)BB*HH*NN*DHH];
__device__ float g_O[(size_t)MTOT*DD];
__device__ float g_gate[(size_t)MTOT*HH];
__device__ float g_Xc[(size_t)MTOT*DD];     // tf32-rounded copy of x
__device__ float g_WqT[(size_t)DD*DD];
__device__ float g_WkT[(size_t)DD*DD];
__device__ float g_WvT[(size_t)DD*DD];
__device__ float g_WoT[(size_t)DD*DD];

// ================= helpers =================
__device__ __forceinline__ float tf32r(float x) {
    uint32_t u;
    asm("cvt.rna.tf32.f32 %0, %1;" : "=r"(u) : "f"(x));
    return __uint_as_float(u);
}
__device__ __forceinline__ void cp16(uint32_t dst, const void* src) {
    asm volatile("cp.async.cg.shared.global [%0], [%1], 16;" :: "r"(dst), "l"(src));
}
__device__ __forceinline__ void cp_commit() { asm volatile("cp.async.commit_group;" ::: "memory"); }
template<int N> __device__ __forceinline__ void cp_wait() {
    asm volatile("cp.async.wait_group %0;" :: "n"(N) : "memory");
}
__device__ __forceinline__ uint32_t smem_u32(const void* p) {
    uint32_t a;
    asm("{ .reg .u64 t; cvta.to.shared.u64 t, %1; cvt.u32.u64 %0, t; }" : "=r"(a) : "l"(p));
    return a;
}
__device__ __forceinline__ void mma_tf32(float* c, const uint32_t* a, const uint32_t* b) {
    asm volatile("mma.sync.aligned.m16n8k8.row.col.f32.tf32.tf32.f32 "
                 "{%0,%1,%2,%3}, {%4,%5,%6,%7}, {%8,%9}, {%0,%1,%2,%3};"
                 : "+f"(c[0]), "+f"(c[1]), "+f"(c[2]), "+f"(c[3])
                 : "r"(a[0]), "r"(a[1]), "r"(a[2]), "r"(a[3]), "r"(b[0]), "r"(b[1]));
}

// ================= transpose (+ tf32 rounding): Wt[n][k] = W[k][n] ==========
__global__ __launch_bounds__(256)
void transpose_kernel(const float* __restrict__ W, float* __restrict__ Wt)
{
    __shared__ float t[32][33];
    int x = blockIdx.x * 32 + threadIdx.x;
    int y0 = blockIdx.y * 32 + threadIdx.y;
#pragma unroll
    for (int j = 0; j < 32; j += 8)
        t[threadIdx.y + j][threadIdx.x] = W[(size_t)(y0 + j) * DD + x];
    __syncthreads();
    int xo = blockIdx.y * 32 + threadIdx.x;
    int yo = blockIdx.x * 32 + threadIdx.y;
#pragma unroll
    for (int j = 0; j < 32; j += 8)
        Wt[(size_t)(yo + j) * DD + xo] = tf32r(t[threadIdx.x][threadIdx.y + j]);
}

// tf32-round x into g_Xc
__global__ void convert_x_kernel(const float* __restrict__ x)
{
    int i = blockIdx.x * blockDim.x + threadIdx.x;
    float4 v = *(const float4*)(x + (size_t)i * 4);
    v.x = tf32r(v.x); v.y = tf32r(v.y); v.z = tf32r(v.z); v.w = tf32r(v.w);
    *(float4*)(g_Xc + (size_t)i * 4) = v;
}

// ================= tf32 mma.sync GEMM =======================================
// C[4096,2048] = A[4096,2048] x Bt[2048(n),2048(k)]^T
// block 128x128, BK=32, 8 warps (2m x 4n), warp tile 64x32, frags 4x4 m16n8k8
#define BK 32
#define PADF 36                       // floats per smem row (conflict-free)
#define STG_F (128 * PADF)            // 4608 floats per stage per matrix
#define NCH (DD / BK)                 // 64
#define GEMM_SMEM (4 * STG_F * 4)     // 2 stages x (A+B) = 73728 B

__device__ __forceinline__ void g_load_stage(float* sA, float* sB, int s,
                                             const float* __restrict__ A,
                                             const float* __restrict__ Bt,
                                             int row0, int col0, int k0, int tid)
{
    int row = tid >> 1;               // 0..127
    int half = tid & 1;               // 16-float half of the 32-float row
    uint32_t a_s = smem_u32(sA) + (s * STG_F + row * PADF + half * 16) * 4;
    uint32_t b_s = smem_u32(sB) + (s * STG_F + row * PADF + half * 16) * 4;
    const float* ag = A  + (size_t)(row0 + row) * DD + k0 + half * 16;
    const float* bg = Bt + (size_t)(col0 + row) * DD + k0 + half * 16;
#pragma unroll
    for (int j = 0; j < 4; j++) {
        cp16(a_s + j * 16, ag + j * 4);
        cp16(b_s + j * 16, bg + j * 4);
    }
}

template<bool SPLIT>
__global__ __launch_bounds__(256, 2)
void gemm_mma_kernel(const float* __restrict__ A, const float* __restrict__ Bt,
                     float* __restrict__ C)
{
    extern __shared__ float sm[];
    float* sA = sm;                   // [2][128][36]
    float* sB = sm + 2 * STG_F;       // [2][128][36]

    const int tid = threadIdx.x;
    const int wid = tid >> 5, lane = tid & 31;
    const int g = lane >> 2, tg = lane & 3;
    const int wm = wid & 1, wn = wid >> 1;          // 2 x 4 warp grid
    const int row0 = blockIdx.y * 128;
    const int col0 = blockIdx.x * 128;

    float c[4][4][4];
#pragma unroll
    for (int mf = 0; mf < 4; mf++)
#pragma unroll
        for (int nf = 0; nf < 4; nf++)
#pragma unroll
            for (int r = 0; r < 4; r++) c[mf][nf][r] = 0.f;

    g_load_stage(sA, sB, 0, A, Bt, row0, col0, 0, tid);
    cp_commit();

    for (int i = 0; i < NCH; i++) {
        if (i + 1 < NCH) {
            g_load_stage(sA, sB, (i + 1) & 1, A, Bt, row0, col0, (i + 1) * BK, tid);
            cp_commit();
            cp_wait<1>();
        } else {
            cp_wait<0>();
        }
        __syncthreads();

        const float* As = sA + (i & 1) * STG_F;
        const float* Bs = sB + (i & 1) * STG_F;
#pragma unroll
        for (int ks = 0; ks < 4; ks++) {
            int k0 = ks * 8;
            uint32_t af[4][4], bf[4][2];
#pragma unroll
            for (int mf = 0; mf < 4; mf++) {
                int rb = wm * 64 + mf * 16 + g;
                af[mf][0] = __float_as_uint(As[(rb)     * PADF + k0 + tg]);
                af[mf][1] = __float_as_uint(As[(rb + 8) * PADF + k0 + tg]);
                af[mf][2] = __float_as_uint(As[(rb)     * PADF + k0 + tg + 4]);
                af[mf][3] = __float_as_uint(As[(rb + 8) * PADF + k0 + tg + 4]);
            }
#pragma unroll
            for (int nf = 0; nf < 4; nf++) {
                int cb = wn * 32 + nf * 8 + g;
                bf[nf][0] = __float_as_uint(Bs[cb * PADF + k0 + tg]);
                bf[nf][1] = __float_as_uint(Bs[cb * PADF + k0 + tg + 4]);
            }
#pragma unroll
            for (int mf = 0; mf < 4; mf++)
#pragma unroll
                for (int nf = 0; nf < 4; nf++)
                    mma_tf32(c[mf][nf], af[mf], bf[nf]);
        }
        __syncthreads();
    }

    // epilogue
#pragma unroll
    for (int mf = 0; mf < 4; mf++) {
#pragma unroll
        for (int nf = 0; nf < 4; nf++) {
            int col = col0 + wn * 32 + nf * 8 + tg * 2;
#pragma unroll
            for (int half = 0; half < 2; half++) {
                int m = row0 + wm * 64 + mf * 16 + g + half * 8;
                float* dp;
                if (SPLIT) {
                    int b = m >> 11, n = m & (NN - 1);
                    int h = col >> 7, dh = col & (DHH - 1);
                    dp = C + (((size_t)(b * HH + h) * NN + n) * DHH + dh);
                } else {
                    dp = C + (size_t)m * DD + col;
                }
                dp[0] = c[mf][nf][half * 2];
                dp[1] = c[mf][nf][half * 2 + 1];
            }
        }
    }
}

// ================= RoPE (scale folded into Q) =================
__global__ void rope_kernel(const float* __restrict__ freqs)
{
    int idx = blockIdx.x * blockDim.x + threadIdx.x;
    const int total = BB * HH * NN * 64;
    if (idx >= total) return;
    int half = idx & 63;
    int n = (idx >> 6) & (NN - 1);
    int bh = idx >> 17;

    const float* f = freqs + (size_t)n * DHH;
    float c1 = cosf(f[half]),      s1 = sinf(f[half]);
    float c2 = cosf(f[half + 64]), s2 = sinf(f[half + 64]);

    size_t base = ((size_t)bh * NN + n) * DHH;
    float q1 = g_Q[base + half], q2 = g_Q[base + half + 64];
    g_Q[base + half]      = (q1 * c1 - q2 * s1) * SCALE;
    g_Q[base + half + 64] = (q2 * c2 + q1 * s2) * SCALE;
    float k1 = g_K[base + half], k2 = g_K[base + half + 64];
    g_K[base + half]      = k1 * c1 - k2 * s1;
    g_K[base + half + 64] = k2 * c2 + k1 * s2;
}

// ================= Gate =================
__global__ void gate_kernel(const float* __restrict__ x,
                            const float* __restrict__ Wg,
                            const float* __restrict__ bg)
{
    int gw = (blockIdx.x * blockDim.x + threadIdx.x) >> 5;
    int lane = threadIdx.x & 31;
    if (gw >= MTOT) return;

    const float* xr = x + (size_t)gw * DD;
    float acc[HH];
#pragma unroll
    for (int h = 0; h < HH; h++) acc[h] = 0.f;

    for (int k = lane; k < DD; k += 32) {
        float xv = xr[k];
        const float* w = Wg + (size_t)k * HH;
#pragma unroll
        for (int h = 0; h < HH; h++) acc[h] = fmaf(xv, w[h], acc[h]);
    }
#pragma unroll
    for (int h = 0; h < HH; h++) {
#pragma unroll
        for (int off = 16; off > 0; off >>= 1)
            acc[h] += __shfl_xor_sync(0xffffffffu, acc[h], off);
    }
    if (lane == 0) {
#pragma unroll
        for (int h = 0; h < HH; h++)
            g_gate[(size_t)gw * HH + h] = 1.f / (1.f + expf(-(acc[h] + bg[h])));
    }
}

// ================= Flash attention (fp32) =================
#define QS_STRIDE 130
#define KS_STRIDE 130
#define SS_STRIDE 66
#define FLASH_SMEM ((64*QS_STRIDE + 64*KS_STRIDE + 64*128 + 64*SS_STRIDE) * 4)

__global__ __launch_bounds__(256)
void flash_kernel()
{
    extern __shared__ float sm[];
    float* Qs = sm;
    float* Ks = Qs + 64 * QS_STRIDE;
    float* Vs = Ks + 64 * KS_STRIDE;
    float* Ss = Vs + 64 * 128;

    const int tid = threadIdx.x;
    const int tx = tid & 15, ty = tid >> 4;

    const int bh = blockIdx.x >> 5;
    const int n0 = (blockIdx.x & 31) * 64;

    const float* Qg = g_Q + ((size_t)bh * NN + n0) * DHH;
    const float* Kg = g_K + (size_t)bh * NN * DHH;
    const float* Vg = g_V + (size_t)bh * NN * DHH;

    {
        int c4 = (tid & 31) * 4;
        int r0 = tid >> 5;
#pragma unroll
        for (int p = 0; p < 8; p++) {
            int r = r0 + p * 8;
            float4 v = *(const float4*)(Qg + (size_t)r * DHH + c4);
            Qs[r * QS_STRIDE + c4 + 0] = v.x;
            Qs[r * QS_STRIDE + c4 + 1] = v.y;
            Qs[r * QS_STRIDE + c4 + 2] = v.z;
            Qs[r * QS_STRIDE + c4 + 3] = v.w;
        }
    }

    float mrow[4], lrow[4], o[4][8];
#pragma unroll
    for (int i = 0; i < 4; i++) {
        mrow[i] = -1e30f; lrow[i] = 0.f;
#pragma unroll
        for (int c = 0; c < 8; c++) o[i][c] = 0.f;
    }

    for (int kt = 0; kt < NN / 64; kt++) {
        __syncthreads();
        {
            int c4 = (tid & 31) * 4;
            int r0 = tid >> 5;
            const float* Kt = Kg + (size_t)kt * 64 * DHH;
            const float* Vt = Vg + (size_t)kt * 64 * DHH;
#pragma unroll
            for (int p = 0; p < 8; p++) {
                int r = r0 + p * 8;
                float4 kv = *(const float4*)(Kt + (size_t)r * DHH + c4);
                Ks[r * KS_STRIDE + c4 + 0] = kv.x;
                Ks[r * KS_STRIDE + c4 + 1] = kv.y;
                Ks[r * KS_STRIDE + c4 + 2] = kv.z;
                Ks[r * KS_STRIDE + c4 + 3] = kv.w;
                *(float4*)&Vs[r * 128 + c4] = *(const float4*)(Vt + (size_t)r * DHH + c4);
            }
        }
        __syncthreads();

        float s[4][4];
#pragma unroll
        for (int i = 0; i < 4; i++)
#pragma unroll
            for (int j = 0; j < 4; j++) s[i][j] = 0.f;

#pragma unroll 4
        for (int dh = 0; dh < DHH; dh++) {
            float q0 = Qs[(ty * 4 + 0) * QS_STRIDE + dh];
            float q1 = Qs[(ty * 4 + 1) * QS_STRIDE + dh];
            float q2 = Qs[(ty * 4 + 2) * QS_STRIDE + dh];
            float q3 = Qs[(ty * 4 + 3) * QS_STRIDE + dh];
            float k0 = Ks[(tx)      * KS_STRIDE + dh];
            float k1 = Ks[(tx + 16) * KS_STRIDE + dh];
            float k2 = Ks[(tx + 32) * KS_STRIDE + dh];
            float k3 = Ks[(tx + 48) * KS_STRIDE + dh];
            s[0][0] = fmaf(q0, k0, s[0][0]); s[0][1] = fmaf(q0, k1, s[0][1]);
            s[0][2] = fmaf(q0, k2, s[0][2]); s[0][3] = fmaf(q0, k3, s[0][3]);
            s[1][0] = fmaf(q1, k0, s[1][0]); s[1][1] = fmaf(q1, k1, s[1][1]);
            s[1][2] = fmaf(q1, k2, s[1][2]); s[1][3] = fmaf(q1, k3, s[1][3]);
            s[2][0] = fmaf(q2, k0, s[2][0]); s[2][1] = fmaf(q2, k1, s[2][1]);
            s[2][2] = fmaf(q2, k2, s[2][2]); s[2][3] = fmaf(q2, k3, s[2][3]);
            s[3][0] = fmaf(q3, k0, s[3][0]); s[3][1] = fmaf(q3, k1, s[3][1]);
            s[3][2] = fmaf(q3, k2, s[3][2]); s[3][3] = fmaf(q3, k3, s[3][3]);
        }

#pragma unroll
        for (int i = 0; i < 4; i++) {
            float mx = fmaxf(fmaxf(s[i][0], s[i][1]), fmaxf(s[i][2], s[i][3]));
            mx = fmaxf(mx, __shfl_xor_sync(0xffffffffu, mx, 1));
            mx = fmaxf(mx, __shfl_xor_sync(0xffffffffu, mx, 2));
            mx = fmaxf(mx, __shfl_xor_sync(0xffffffffu, mx, 4));
            mx = fmaxf(mx, __shfl_xor_sync(0xffffffffu, mx, 8));
            float mnew = fmaxf(mrow[i], mx);
            float p0 = __expf(s[i][0] - mnew);
            float p1 = __expf(s[i][1] - mnew);
            float p2 = __expf(s[i][2] - mnew);
            float p3 = __expf(s[i][3] - mnew);
            float sum = p0 + p1 + p2 + p3;
            sum += __shfl_xor_sync(0xffffffffu, sum, 1);
            sum += __shfl_xor_sync(0xffffffffu, sum, 2);
            sum += __shfl_xor_sync(0xffffffffu, sum, 4);
            sum += __shfl_xor_sync(0xffffffffu, sum, 8);
            float alpha = __expf(mrow[i] - mnew);
            lrow[i] = lrow[i] * alpha + sum;
            mrow[i] = mnew;
#pragma unroll
            for (int c = 0; c < 8; c++) o[i][c] *= alpha;
            int rb = (ty * 4 + i) * SS_STRIDE + tx;
            Ss[rb]      = p0;
            Ss[rb + 16] = p1;
            Ss[rb + 32] = p2;
            Ss[rb + 48] = p3;
        }
        __syncthreads();

#pragma unroll 2
        for (int j = 0; j < 64; j++) {
            float p0 = Ss[(ty * 4 + 0) * SS_STRIDE + j];
            float p1 = Ss[(ty * 4 + 1) * SS_STRIDE + j];
            float p2 = Ss[(ty * 4 + 2) * SS_STRIDE + j];
            float p3 = Ss[(ty * 4 + 3) * SS_STRIDE + j];
            float4 v0 = *(float4*)&Vs[j * 128 + tx * 8];
            float4 v1 = *(float4*)&Vs[j * 128 + tx * 8 + 4];
            o[0][0] = fmaf(p0, v0.x, o[0][0]); o[0][1] = fmaf(p0, v0.y, o[0][1]);
            o[0][2] = fmaf(p0, v0.z, o[0][2]); o[0][3] = fmaf(p0, v0.w, o[0][3]);
            o[0][4] = fmaf(p0, v1.x, o[0][4]); o[0][5] = fmaf(p0, v1.y, o[0][5]);
            o[0][6] = fmaf(p0, v1.z, o[0][6]); o[0][7] = fmaf(p0, v1.w, o[0][7]);
            o[1][0] = fmaf(p1, v0.x, o[1][0]); o[1][1] = fmaf(p1, v0.y, o[1][1]);
            o[1][2] = fmaf(p1, v0.z, o[1][2]); o[1][3] = fmaf(p1, v0.w, o[1][3]);
            o[1][4] = fmaf(p1, v1.x, o[1][4]); o[1][5] = fmaf(p1, v1.y, o[1][5]);
            o[1][6] = fmaf(p1, v1.z, o[1][6]); o[1][7] = fmaf(p1, v1.w, o[1][7]);
            o[2][0] = fmaf(p2, v0.x, o[2][0]); o[2][1] = fmaf(p2, v0.y, o[2][1]);
            o[2][2] = fmaf(p2, v0.z, o[2][2]); o[2][3] = fmaf(p2, v0.w, o[2][3]);
            o[2][4] = fmaf(p2, v1.x, o[2][4]); o[2][5] = fmaf(p2, v1.y, o[2][5]);
            o[2][6] = fmaf(p2, v1.z, o[2][6]); o[2][7] = fmaf(p2, v1.w, o[2][7]);
            o[3][0] = fmaf(p3, v0.x, o[3][0]); o[3][1] = fmaf(p3, v0.y, o[3][1]);
            o[3][2] = fmaf(p3, v0.z, o[3][2]); o[3][3] = fmaf(p3, v0.w, o[3][3]);
            o[3][4] = fmaf(p3, v1.x, o[3][4]); o[3][5] = fmaf(p3, v1.y, o[3][5]);
            o[3][6] = fmaf(p3, v1.z, o[3][6]); o[3][7] = fmaf(p3, v1.w, o[3][7]);
        }
    }

    // epilogue: normalize, gate, merge heads; tf32-round for the out-proj GEMM
    const int b = bh >> 4, h = bh & 15;
#pragma unroll
    for (int i = 0; i < 4; i++) {
        int n = n0 + ty * 4 + i;
        float g = g_gate[((size_t)(b * NN + n)) * HH + h];
        float sc = g / lrow[i];
        float* dst = g_O + ((size_t)(b * NN + n) * DD + h * DHH + tx * 8);
        *(float4*)dst       = make_float4(tf32r(o[i][0] * sc), tf32r(o[i][1] * sc),
                                          tf32r(o[i][2] * sc), tf32r(o[i][3] * sc));
        *(float4*)(dst + 4) = make_float4(tf32r(o[i][4] * sc), tf32r(o[i][5] * sc),
                                          tf32r(o[i][6] * sc), tf32r(o[i][7] * sc));
    }
}

// =====================================================================
extern "C" void kernel_launch(void* const* d_in, const int* in_sizes, int n_in,
                              void* d_out, int out_size)
{
    const float* x    = (const float*)d_in[0];
    const float* rope = (const float*)d_in[1];
    const float* Wq   = (const float*)d_in[2];
    const float* Wk   = (const float*)d_in[3];
    const float* Wv   = (const float*)d_in[4];
    const float* Wg   = (const float*)d_in[5];
    const float* bg   = (const float*)d_in[6];
    const float* Wo   = (const float*)d_in[7];
    float* out = (float*)d_out;

    float *wqT, *wkT, *wvT, *woT, *gq, *gk, *gv, *go, *xc;
    cudaGetSymbolAddress((void**)&wqT, g_WqT);
    cudaGetSymbolAddress((void**)&wkT, g_WkT);
    cudaGetSymbolAddress((void**)&wvT, g_WvT);
    cudaGetSymbolAddress((void**)&woT, g_WoT);
    cudaGetSymbolAddress((void**)&gq, g_Q);
    cudaGetSymbolAddress((void**)&gk, g_K);
    cudaGetSymbolAddress((void**)&gv, g_V);
    cudaGetSymbolAddress((void**)&go, g_O);
    cudaGetSymbolAddress((void**)&xc, g_Xc);

    cudaFuncSetAttribute(flash_kernel,
                         cudaFuncAttributeMaxDynamicSharedMemorySize, FLASH_SMEM);
    cudaFuncSetAttribute(gemm_mma_kernel<true>,
                         cudaFuncAttributeMaxDynamicSharedMemorySize, GEMM_SMEM);
    cudaFuncSetAttribute(gemm_mma_kernel<false>,
                         cudaFuncAttributeMaxDynamicSharedMemorySize, GEMM_SMEM);

    // 0) weight transposes (+tf32 round) and x conversion
    dim3 tg(DD / 32, DD / 32);
    dim3 tb(32, 8);
    transpose_kernel<<<tg, tb>>>(Wq, wqT);
    transpose_kernel<<<tg, tb>>>(Wk, wkT);
    transpose_kernel<<<tg, tb>>>(Wv, wvT);
    transpose_kernel<<<tg, tb>>>(Wo, woT);
    convert_x_kernel<<<(MTOT * DD / 4 + 255) / 256, 256>>>(x);

    // 1) QKV projections (tf32 mma.sync, split-head store)
    dim3 gg(DD / 128, MTOT / 128);
    gemm_mma_kernel<true><<<gg, 256, GEMM_SMEM>>>(xc, wqT, gq);
    gemm_mma_kernel<true><<<gg, 256, GEMM_SMEM>>>(xc, wkT, gk);
    gemm_mma_kernel<true><<<gg, 256, GEMM_SMEM>>>(xc, wvT, gv);

    // 2) RoPE
    {
        int total = BB * HH * NN * 64;
        rope_kernel<<<(total + 255) / 256, 256>>>(rope);
    }

    // 3) head gates
    gate_kernel<<<(MTOT * 32 + 255) / 256, 256>>>(x, Wg, bg);

    // 4) flash attention + gating + head merge
    flash_kernel<<<BB * HH * (NN / 64), 256, FLASH_SMEM>>>();

    // 5) output projection (tf32 mma.sync)
    gemm_mma_kernel<false><<<gg, 256, GEMM_SMEM>>>(go, woT, out);
}

// round 4
// speedup vs baseline: 2.1861x; 1.5698x over previous
#include <cuda_runtime.h>
#include <math.h>
#include <stdint.h>

// Problem constants
#define BB   2
#define NN   2048
#define DD   2048
#define HH   16
#define DHH  128
#define MTOT (BB*NN)
#define SCALE 0.08838834764831845f  // DH^-0.5

// ---------------- device scratch ----------------
__device__ float g_Q[(size_t)BB*HH*NN*DHH];
__device__ float g_K[(size_t)BB*HH*NN*DHH];
__device__ float g_V[(size_t)BB*HH*NN*DHH];
__device__ float g_O[(size_t)MTOT*DD];
__device__ float g_gate[(size_t)MTOT*HH];
__device__ float g_Xc[(size_t)MTOT*DD];
__device__ float g_WqT[(size_t)DD*DD];
__device__ float g_WkT[(size_t)DD*DD];
__device__ float g_WvT[(size_t)DD*DD];
__device__ float g_WoT[(size_t)DD*DD];

// ================= helpers =================
__device__ __forceinline__ float tf32r(float x) {
    uint32_t u;
    asm("cvt.rna.tf32.f32 %0, %1;" : "=r"(u) : "f"(x));
    return __uint_as_float(u);
}
__device__ __forceinline__ void cp16(uint32_t dst, const void* src) {
    asm volatile("cp.async.cg.shared.global [%0], [%1], 16;" :: "r"(dst), "l"(src));
}
__device__ __forceinline__ void cp_commit() { asm volatile("cp.async.commit_group;" ::: "memory"); }
template<int N> __device__ __forceinline__ void cp_wait() {
    asm volatile("cp.async.wait_group %0;" :: "n"(N) : "memory");
}
__device__ __forceinline__ uint32_t smem_u32(const void* p) {
    uint32_t a;
    asm("{ .reg .u64 t; cvta.to.shared.u64 t, %1; cvt.u32.u64 %0, t; }" : "=r"(a) : "l"(p));
    return a;
}
__device__ __forceinline__ void mma_tf32(float* c, const uint32_t* a, const uint32_t* b) {
    asm volatile("mma.sync.aligned.m16n8k8.row.col.f32.tf32.tf32.f32 "
                 "{%0,%1,%2,%3}, {%4,%5,%6,%7}, {%8,%9}, {%0,%1,%2,%3};"
                 : "+f"(c[0]), "+f"(c[1]), "+f"(c[2]), "+f"(c[3])
                 : "r"(a[0]), "r"(a[1]), "r"(a[2]), "r"(a[3]), "r"(b[0]), "r"(b[1]));
}

// ================= transpose (+ tf32 rounding) =================
__global__ __launch_bounds__(256)
void transpose_kernel(const float* __restrict__ W, float* __restrict__ Wt)
{
    __shared__ float t[32][33];
    int x = blockIdx.x * 32 + threadIdx.x;
    int y0 = blockIdx.y * 32 + threadIdx.y;
#pragma unroll
    for (int j = 0; j < 32; j += 8)
        t[threadIdx.y + j][threadIdx.x] = W[(size_t)(y0 + j) * DD + x];
    __syncthreads();
    int xo = blockIdx.y * 32 + threadIdx.x;
    int yo = blockIdx.x * 32 + threadIdx.y;
#pragma unroll
    for (int j = 0; j < 32; j += 8)
        Wt[(size_t)(yo + j) * DD + xo] = tf32r(t[threadIdx.x][threadIdx.y + j]);
}

__global__ void convert_x_kernel(const float* __restrict__ x)
{
    int i = blockIdx.x * blockDim.x + threadIdx.x;
    float4 v = *(const float4*)(x + (size_t)i * 4);
    v.x = tf32r(v.x); v.y = tf32r(v.y); v.z = tf32r(v.z); v.w = tf32r(v.w);
    *(float4*)(g_Xc + (size_t)i * 4) = v;
}

// ================= tf32 mma.sync GEMM (R3, + optional output rounding) ======
#define BKG 32
#define PADF 36
#define STG_F (128 * PADF)
#define NCH (DD / BKG)
#define GEMM_SMEM (4 * STG_F * 4)

__device__ __forceinline__ void g_load_stage(float* sA, float* sB, int s,
                                             const float* __restrict__ A,
                                             const float* __restrict__ Bt,
                                             int row0, int col0, int k0, int tid)
{
    int row = tid >> 1;
    int half = tid & 1;
    uint32_t a_s = smem_u32(sA) + (s * STG_F + row * PADF + half * 16) * 4;
    uint32_t b_s = smem_u32(sB) + (s * STG_F + row * PADF + half * 16) * 4;
    const float* ag = A  + (size_t)(row0 + row) * DD + k0 + half * 16;
    const float* bg = Bt + (size_t)(col0 + row) * DD + k0 + half * 16;
#pragma unroll
    for (int j = 0; j < 4; j++) {
        cp16(a_s + j * 16, ag + j * 4);
        cp16(b_s + j * 16, bg + j * 4);
    }
}

template<bool SPLIT, bool RND>
__global__ __launch_bounds__(256, 2)
void gemm_mma_kernel(const float* __restrict__ A, const float* __restrict__ Bt,
                     float* __restrict__ C)
{
    extern __shared__ float sm[];
    float* sA = sm;
    float* sB = sm + 2 * STG_F;

    const int tid = threadIdx.x;
    const int wid = tid >> 5, lane = tid & 31;
    const int g = lane >> 2, tg = lane & 3;
    const int wm = wid & 1, wn = wid >> 1;
    const int row0 = blockIdx.y * 128;
    const int col0 = blockIdx.x * 128;

    float c[4][4][4];
#pragma unroll
    for (int mf = 0; mf < 4; mf++)
#pragma unroll
        for (int nf = 0; nf < 4; nf++)
#pragma unroll
            for (int r = 0; r < 4; r++) c[mf][nf][r] = 0.f;

    g_load_stage(sA, sB, 0, A, Bt, row0, col0, 0, tid);
    cp_commit();

    for (int i = 0; i < NCH; i++) {
        if (i + 1 < NCH) {
            g_load_stage(sA, sB, (i + 1) & 1, A, Bt, row0, col0, (i + 1) * BKG, tid);
            cp_commit();
            cp_wait<1>();
        } else {
            cp_wait<0>();
        }
        __syncthreads();

        const float* As = sA + (i & 1) * STG_F;
        const float* Bs = sB + (i & 1) * STG_F;
#pragma unroll
        for (int ks = 0; ks < 4; ks++) {
            int k0 = ks * 8;
            uint32_t af[4][4], bf[4][2];
#pragma unroll
            for (int mf = 0; mf < 4; mf++) {
                int rb = wm * 64 + mf * 16 + g;
                af[mf][0] = __float_as_uint(As[(rb)     * PADF + k0 + tg]);
                af[mf][1] = __float_as_uint(As[(rb + 8) * PADF + k0 + tg]);
                af[mf][2] = __float_as_uint(As[(rb)     * PADF + k0 + tg + 4]);
                af[mf][3] = __float_as_uint(As[(rb + 8) * PADF + k0 + tg + 4]);
            }
#pragma unroll
            for (int nf = 0; nf < 4; nf++) {
                int cb = wn * 32 + nf * 8 + g;
                bf[nf][0] = __float_as_uint(Bs[cb * PADF + k0 + tg]);
                bf[nf][1] = __float_as_uint(Bs[cb * PADF + k0 + tg + 4]);
            }
#pragma unroll
            for (int mf = 0; mf < 4; mf++)
#pragma unroll
                for (int nf = 0; nf < 4; nf++)
                    mma_tf32(c[mf][nf], af[mf], bf[nf]);
        }
        __syncthreads();
    }

#pragma unroll
    for (int mf = 0; mf < 4; mf++) {
#pragma unroll
        for (int nf = 0; nf < 4; nf++) {
            int col = col0 + wn * 32 + nf * 8 + tg * 2;
#pragma unroll
            for (int half = 0; half < 2; half++) {
                int m = row0 + wm * 64 + mf * 16 + g + half * 8;
                float* dp;
                if (SPLIT) {
                    int b = m >> 11, n = m & (NN - 1);
                    int h = col >> 7, dh = col & (DHH - 1);
                    dp = C + (((size_t)(b * HH + h) * NN + n) * DHH + dh);
                } else {
                    dp = C + (size_t)m * DD + col;
                }
                float v0 = c[mf][nf][half * 2], v1 = c[mf][nf][half * 2 + 1];
                if (RND) { v0 = tf32r(v0); v1 = tf32r(v1); }
                dp[0] = v0;
                dp[1] = v1;
            }
        }
    }
}

// ================= RoPE (scale folded into Q, outputs tf32-rounded) =========
__global__ void rope_kernel(const float* __restrict__ freqs)
{
    int idx = blockIdx.x * blockDim.x + threadIdx.x;
    const int total = BB * HH * NN * 64;
    if (idx >= total) return;
    int half = idx & 63;
    int n = (idx >> 6) & (NN - 1);
    int bh = idx >> 17;

    const float* f = freqs + (size_t)n * DHH;
    float c1 = cosf(f[half]),      s1 = sinf(f[half]);
    float c2 = cosf(f[half + 64]), s2 = sinf(f[half + 64]);

    size_t base = ((size_t)bh * NN + n) * DHH;
    float q1 = g_Q[base + half], q2 = g_Q[base + half + 64];
    g_Q[base + half]      = tf32r((q1 * c1 - q2 * s1) * SCALE);
    g_Q[base + half + 64] = tf32r((q2 * c2 + q1 * s2) * SCALE);
    float k1 = g_K[base + half], k2 = g_K[base + half + 64];
    g_K[base + half]      = tf32r(k1 * c1 - k2 * s1);
    g_K[base + half + 64] = tf32r(k2 * c2 + k1 * s2);
}

// ================= Gate =================
__global__ void gate_kernel(const float* __restrict__ x,
                            const float* __restrict__ Wg,
                            const float* __restrict__ bg)
{
    int gw = (blockIdx.x * blockDim.x + threadIdx.x) >> 5;
    int lane = threadIdx.x & 31;
    if (gw >= MTOT) return;

    const float* xr = x + (size_t)gw * DD;
    float acc[HH];
#pragma unroll
    for (int h = 0; h < HH; h++) acc[h] = 0.f;

    for (int k = lane; k < DD; k += 32) {
        float xv = xr[k];
        const float* w = Wg + (size_t)k * HH;
#pragma unroll
        for (int h = 0; h < HH; h++) acc[h] = fmaf(xv, w[h], acc[h]);
    }
#pragma unroll
    for (int h = 0; h < HH; h++) {
#pragma unroll
        for (int off = 16; off > 0; off >>= 1)
            acc[h] += __shfl_xor_sync(0xffffffffu, acc[h], off);
    }
    if (lane == 0) {
#pragma unroll
        for (int h = 0; h < HH; h++)
            g_gate[(size_t)gw * HH + h] = 1.f / (1.f + expf(-(acc[h] + bg[h])));
    }
}

// ================= Flash attention (tf32 mma.sync) ==========================
// Br=128 q-rows/CTA, Bc=64 keys/iter, 8 warps x 16 full rows each.
// Q frags in registers; K/V double-buffered cp.async; P via smem (warp-local).
#define KSTR 132                       // K/V smem row stride (floats)
#define PSTR 68                        // P smem row stride
#define KV_F (64 * KSTR)               // 8448 floats per stage per matrix
#define FL_KS0 0
#define FL_KS1 (FL_KS0 + KV_F)
#define FL_VS0 (FL_KS1 + KV_F)
#define FL_VS1 (FL_VS0 + KV_F)
#define FL_PS  (FL_VS1 + KV_F)
#define FLASH_SMEM ((FL_PS + 128 * PSTR) * 4)   // 169,984 B
#define NT (NN / 64)                   // 32 key tiles

__device__ __forceinline__ void fl_load_kv(uint32_t sb, int stage,
                                           const float* __restrict__ Kg,
                                           const float* __restrict__ Vg,
                                           int kt, int tid)
{
    int row = tid >> 2;                // 0..63
    int part = tid & 3;                // 32-float quarter
    uint32_t ks = sb + (uint32_t)(FL_KS0 + stage * KV_F + row * KSTR + part * 32) * 4;
    uint32_t vs = sb + (uint32_t)(FL_VS0 + stage * KV_F + row * KSTR + part * 32) * 4;
    const float* kg = Kg + (size_t)(kt * 64 + row) * DHH + part * 32;
    const float* vg = Vg + (size_t)(kt * 64 + row) * DHH + part * 32;
#pragma unroll
    for (int j = 0; j < 8; j++) {
        cp16(ks + j * 16, kg + j * 4);
        cp16(vs + j * 16, vg + j * 4);
    }
}

__global__ __launch_bounds__(256, 1)
void flash_tc_kernel()
{
    extern __shared__ float sm[];
    uint32_t sb = smem_u32(sm);
    float* Ps = sm + FL_PS;

    const int tid = threadIdx.x;
    const int wid = tid >> 5, lane = tid & 31;
    const int g = lane >> 2, tg = lane & 3;
    const int m0 = wid * 16;                       // warp's rows within tile
    const int qt0 = blockIdx.x * 128;              // q-tile base
    const int bh = blockIdx.y;

    const float* Qg = g_Q + (size_t)bh * NN * DHH;
    const float* Kg = g_K + (size_t)bh * NN * DHH;
    const float* Vg = g_V + (size_t)bh * NN * DHH;

    // ---- stage Q tile through smem (coalesced), harvest frags to registers
    uint32_t aq[16][4];
    {
        float* stg = sm + FL_KS0;                  // reuse K stage-0 buffer
#pragma unroll
        for (int chunk = 0; chunk < 2; chunk++) {
            int row = tid >> 2, part = tid & 3;
            const float* qg = Qg + (size_t)(qt0 + chunk * 64 + row) * DHH + part * 32;
#pragma unroll
            for (int j = 0; j < 8; j++)
                *(float4*)&stg[row * KSTR + part * 32 + j * 4] = *(const float4*)(qg + j * 4);
            __syncthreads();
            if (m0 >= chunk * 64 && m0 < chunk * 64 + 64) {
                int lm = m0 - chunk * 64;
#pragma unroll
                for (int ks = 0; ks < 16; ks++) {
                    aq[ks][0] = __float_as_uint(stg[(lm + g)     * KSTR + ks * 8 + tg]);
                    aq[ks][1] = __float_as_uint(stg[(lm + g + 8) * KSTR + ks * 8 + tg]);
                    aq[ks][2] = __float_as_uint(stg[(lm + g)     * KSTR + ks * 8 + tg + 4]);
                    aq[ks][3] = __float_as_uint(stg[(lm + g + 8) * KSTR + ks * 8 + tg + 4]);
                }
            }
            __syncthreads();
        }
    }

    float o[16][4];
#pragma unroll
    for (int nf = 0; nf < 16; nf++)
#pragma unroll
        for (int r = 0; r < 4; r++) o[nf][r] = 0.f;
    float mA = -1e30f, mB = -1e30f, lA = 0.f, lB = 0.f;

    fl_load_kv(sb, 0, Kg, Vg, 0, tid);
    cp_commit();

    for (int kt = 0; kt < NT; kt++) {
        int st = kt & 1;
        cp_wait<0>();
        __syncthreads();
        if (kt + 1 < NT) {
            fl_load_kv(sb, st ^ 1, Kg, Vg, kt + 1, tid);
            cp_commit();
        }

        const float* Ks = sm + FL_KS0 + st * KV_F;
        const float* Vs = sm + FL_VS0 + st * KV_F;

        // ---- S = Q K^T  (16 rows x 64 keys per warp)
        float s[8][4];
#pragma unroll
        for (int nf = 0; nf < 8; nf++)
#pragma unroll
            for (int r = 0; r < 4; r++) s[nf][r] = 0.f;

#pragma unroll
        for (int ks = 0; ks < 16; ks++) {
#pragma unroll
            for (int nf = 0; nf < 8; nf++) {
                uint32_t bf[2];
                bf[0] = __float_as_uint(Ks[(nf * 8 + g) * KSTR + ks * 8 + tg]);
                bf[1] = __float_as_uint(Ks[(nf * 8 + g) * KSTR + ks * 8 + tg + 4]);
                mma_tf32(s[nf], aq[ks], bf);
            }
        }

        // ---- online softmax (rows g and g+8; reduce over tg quads)
        float mxA = -1e30f, mxB = -1e30f;
#pragma unroll
        for (int nf = 0; nf < 8; nf++) {
            mxA = fmaxf(mxA, fmaxf(s[nf][0], s[nf][1]));
            mxB = fmaxf(mxB, fmaxf(s[nf][2], s[nf][3]));
        }
        mxA = fmaxf(mxA, __shfl_xor_sync(0xffffffffu, mxA, 1));
        mxA = fmaxf(mxA, __shfl_xor_sync(0xffffffffu, mxA, 2));
        mxB = fmaxf(mxB, __shfl_xor_sync(0xffffffffu, mxB, 1));
        mxB = fmaxf(mxB, __shfl_xor_sync(0xffffffffu, mxB, 2));
        float mnA = fmaxf(mA, mxA), mnB = fmaxf(mB, mxB);
        float alA = __expf(mA - mnA), alB = __expf(mB - mnB);
        mA = mnA; mB = mnB;

        float smA = 0.f, smB = 0.f;
#pragma unroll
        for (int nf = 0; nf < 8; nf++) {
            float p0 = __expf(s[nf][0] - mnA);
            float p1 = __expf(s[nf][1] - mnA);
            float p2 = __expf(s[nf][2] - mnB);
            float p3 = __expf(s[nf][3] - mnB);
            smA += p0 + p1; smB += p2 + p3;
            int cb = nf * 8 + tg * 2;
            Ps[(m0 + g)     * PSTR + cb]     = tf32r(p0);
            Ps[(m0 + g)     * PSTR + cb + 1] = tf32r(p1);
            Ps[(m0 + g + 8) * PSTR + cb]     = tf32r(p2);
            Ps[(m0 + g + 8) * PSTR + cb + 1] = tf32r(p3);
        }
        smA += __shfl_xor_sync(0xffffffffu, smA, 1);
        smA += __shfl_xor_sync(0xffffffffu, smA, 2);
        smB += __shfl_xor_sync(0xffffffffu, smB, 1);
        smB += __shfl_xor_sync(0xffffffffu, smB, 2);
        lA = lA * alA + smA;
        lB = lB * alB + smB;

#pragma unroll
        for (int nf = 0; nf < 16; nf++) {
            o[nf][0] *= alA; o[nf][1] *= alA;
            o[nf][2] *= alB; o[nf][3] *= alB;
        }
        __syncwarp();

        // ---- O += P V   (A=P frags from smem, B=V frags from smem)
        uint32_t ap[8][4];
#pragma unroll
        for (int ks = 0; ks < 8; ks++) {
            ap[ks][0] = __float_as_uint(Ps[(m0 + g)     * PSTR + ks * 8 + tg]);
            ap[ks][1] = __float_as_uint(Ps[(m0 + g + 8) * PSTR + ks * 8 + tg]);
            ap[ks][2] = __float_as_uint(Ps[(m0 + g)     * PSTR + ks * 8 + tg + 4]);
            ap[ks][3] = __float_as_uint(Ps[(m0 + g + 8) * PSTR + ks * 8 + tg + 4]);
        }
#pragma unroll
        for (int ks = 0; ks < 8; ks++) {
#pragma unroll
            for (int nf = 0; nf < 16; nf++) {
                uint32_t bf[2];
                bf[0] = __float_as_uint(Vs[(ks * 8 + tg)     * KSTR + nf * 8 + g]);
                bf[1] = __float_as_uint(Vs[(ks * 8 + tg + 4) * KSTR + nf * 8 + g]);
                mma_tf32(o[nf], ap[ks], bf);
            }
        }
        __syncwarp();
    }

    // ---- epilogue: normalize, gate, merge heads, tf32-round for out-proj
    const int b = bh >> 4, h = bh & 15;
    int nAr = qt0 + m0 + g, nBr = nAr + 8;
    float gA = g_gate[((size_t)(b * NN + nAr)) * HH + h];
    float gB = g_gate[((size_t)(b * NN + nBr)) * HH + h];
    float scA = gA / lA, scB = gB / lB;
    float* dA = g_O + ((size_t)(b * NN + nAr) * DD + h * DHH);
    float* dB = g_O + ((size_t)(b * NN + nBr) * DD + h * DHH);
#pragma unroll
    for (int nf = 0; nf < 16; nf++) {
        int dh = nf * 8 + tg * 2;
        *(float2*)(dA + dh) = make_float2(tf32r(o[nf][0] * scA), tf32r(o[nf][1] * scA));
        *(float2*)(dB + dh) = make_float2(tf32r(o[nf][2] * scB), tf32r(o[nf][3] * scB));
    }
}

// =====================================================================
extern "C" void kernel_launch(void* const* d_in, const int* in_sizes, int n_in,
                              void* d_out, int out_size)
{
    const float* x    = (const float*)d_in[0];
    const float* rope = (const float*)d_in[1];
    const float* Wq   = (const float*)d_in[2];
    const float* Wk   = (const float*)d_in[3];
    const float* Wv   = (const float*)d_in[4];
    const float* Wg   = (const float*)d_in[5];
    const float* bg   = (const float*)d_in[6];
    const float* Wo   = (const float*)d_in[7];
    float* out = (float*)d_out;

    float *wqT, *wkT, *wvT, *woT, *gq, *gk, *gv, *go, *xc;
    cudaGetSymbolAddress((void**)&wqT, g_WqT);
    cudaGetSymbolAddress((void**)&wkT, g_WkT);
    cudaGetSymbolAddress((void**)&wvT, g_WvT);
    cudaGetSymbolAddress((void**)&woT, g_WoT);
    cudaGetSymbolAddress((void**)&gq, g_Q);
    cudaGetSymbolAddress((void**)&gk, g_K);
    cudaGetSymbolAddress((void**)&gv, g_V);
    cudaGetSymbolAddress((void**)&go, g_O);
    cudaGetSymbolAddress((void**)&xc, g_Xc);

    cudaFuncSetAttribute(flash_tc_kernel,
                         cudaFuncAttributeMaxDynamicSharedMemorySize, FLASH_SMEM);
    cudaFuncSetAttribute((const void*)gemm_mma_kernel<true, false>,
                         cudaFuncAttributeMaxDynamicSharedMemorySize, GEMM_SMEM);
    cudaFuncSetAttribute((const void*)gemm_mma_kernel<true, true>,
                         cudaFuncAttributeMaxDynamicSharedMemorySize, GEMM_SMEM);
    cudaFuncSetAttribute((const void*)gemm_mma_kernel<false, false>,
                         cudaFuncAttributeMaxDynamicSharedMemorySize, GEMM_SMEM);

    // 0) weight transposes (+tf32 round) and x conversion
    dim3 tg(DD / 32, DD / 32);
    dim3 tb(32, 8);
    transpose_kernel<<<tg, tb>>>(Wq, wqT);
    transpose_kernel<<<tg, tb>>>(Wk, wkT);
    transpose_kernel<<<tg, tb>>>(Wv, wvT);
    transpose_kernel<<<tg, tb>>>(Wo, woT);
    convert_x_kernel<<<(MTOT * DD / 4 + 255) / 256, 256>>>(x);

    // 1) QKV projections (tf32 mma.sync, split-head store; V rounded)
    dim3 gg(DD / 128, MTOT / 128);
    gemm_mma_kernel<true, false><<<gg, 256, GEMM_SMEM>>>(xc, wqT, gq);
    gemm_mma_kernel<true, false><<<gg, 256, GEMM_SMEM>>>(xc, wkT, gk);
    gemm_mma_kernel<true, true ><<<gg, 256, GEMM_SMEM>>>(xc, wvT, gv);

    // 2) RoPE (tf32-rounded outputs)
    {
        int total = BB * HH * NN * 64;
        rope_kernel<<<(total + 255) / 256, 256>>>(rope);
    }

    // 3) head gates
    gate_kernel<<<(MTOT * 32 + 255) / 256, 256>>>(x, Wg, bg);

    // 4) flash attention (tensor cores) + gating + head merge
    {
        dim3 fg(NN / 128, BB * HH);
        flash_tc_kernel<<<fg, 256, FLASH_SMEM>>>();
    }

    // 5) output projection (tf32 mma.sync)
    gemm_mma_kernel<false, false><<<gg, 256, GEMM_SMEM>>>(go, woT, out);
}